// round 7
// baseline (speedup 1.0000x reference)
#include <cuda_runtime.h>
#include <cstdint>

// Problem constants (fixed by the dataset)
#define KMAX      24    // max n-grams per word
#define ROW_BYTES 512   // E=128 fp32

// Zero row: padded slot ids are 0 and must contribute zero (reference zeroes
// table row 0; raw input row 0 is NOT zero). Static .bss device global.
__device__ __align__(256) float g_zero_row[128];

// 256-bit table gather, L2 evict_last (keep the 102MB table resident in the
// 126MB L2 across graph replays; output stream is evict_first below).
__device__ __forceinline__ void ldg256_evl(const void* p, uint64_t d[4]) {
    asm("ld.global.nc.L2::evict_last.v4.b64 {%0,%1,%2,%3}, [%4];"
        : "=l"(d[0]), "=l"(d[1]), "=l"(d[2]), "=l"(d[3])
        : "l"(p));
}

// 256-bit output store, L2 evict_first (pure 16.8MB stream, never re-read).
__device__ __forceinline__ void stg256_evf(void* p, uint64_t q0, uint64_t q1,
                                           uint64_t q2, uint64_t q3) {
    asm volatile("st.global.L2::evict_first.v4.b64 [%0], {%1,%2,%3,%4};"
                 :: "l"(p), "l"(q0), "l"(q1), "l"(q2), "l"(q3)
                 : "memory");
}

// word_idx:      [B*S]      int32
// ngram_ids:     [V, 24]    int32   (slot >= count padded with 0)
// ngram_counts:  [V]        int32
// emb_table:     [NG, 128]  float32
// out:           [B*S, 128] float32 = mean over valid ngram embeddings
//
// One warp per word. Each LDG.256 fetches TWO ngram rows (lanes 0-15 even
// slot, 16-31 odd slot). Each loop iteration issues TWO independent LDG.256s
// (4 slots) before any accumulation -> per-warp MLP=2, halving exposed L2
// latency vs the MLP=1 R6 loop. Trip count ceil(cnt/4) is warp-uniform.
__global__ __launch_bounds__(256, 6)
void ngram_emb_kernel(const int* __restrict__ word_idx,
                      const int* __restrict__ ngram_ids,
                      const int* __restrict__ ngram_counts,
                      const char* __restrict__ emb,    // byte view of table
                      char* __restrict__ out,          // byte view of output
                      int n_words) {
    const int warp = (blockIdx.x * blockDim.x + threadIdx.x) >> 5;
    const int lane = threadIdx.x & 31;
    if (warp >= n_words) return;

    const int half = lane >> 4;       // 0: even slots, 1: odd slots
    const int sub  = lane & 15;       // 32B chunk within the 512B row

    const int w = __ldg(&word_idx[warp]);

    // Lanes 0..23 fetch the 24 ngram ids for this word (coalesced 96B read).
    int id_l = 0;
    if (lane < KMAX) id_l = __ldg(&ngram_ids[w * KMAX + lane]);
    const int cnt = __ldg(&ngram_counts[w]);
    const int quads = (cnt + 3) >> 2;   // warp-uniform trip count (<= 6)

    const char* zrow = (const char*)g_zero_row + sub * 32;

    float acc[8];
    #pragma unroll
    for (int i = 0; i < 8; ++i) acc[i] = 0.f;

    #pragma unroll
    for (int u = 0; u < KMAX / 4; ++u) {
        if (u >= quads) break;          // warp-uniform: no divergence
        const int ida = __shfl_sync(0xffffffffu, id_l, 4 * u + 0 + half);
        const int idb = __shfl_sync(0xffffffffu, id_l, 4 * u + 2 + half);
        // Padded slots (id 0) read the zero row (hot in L1).
        const void* pa = ida ? (const void*)(emb + (size_t)ida * ROW_BYTES + sub * 32)
                             : (const void*)zrow;
        const void* pb = idb ? (const void*)(emb + (size_t)idb * ROW_BYTES + sub * 32)
                             : (const void*)zrow;
        uint64_t da[4], db[4];
        ldg256_evl(pa, da);             // both loads in flight before
        ldg256_evl(pb, db);             // either is consumed
        #pragma unroll
        for (int i = 0; i < 4; ++i) {
            const float ax = __uint_as_float((uint32_t)da[i]);
            const float ay = __uint_as_float((uint32_t)(da[i] >> 32));
            const float bx = __uint_as_float((uint32_t)db[i]);
            const float by = __uint_as_float((uint32_t)(db[i] >> 32));
            acc[2 * i + 0] += (ax + bx);
            acc[2 * i + 1] += (ay + by);
        }
    }

    // Combine even-slot half and odd-slot half.
    #pragma unroll
    for (int i = 0; i < 8; ++i)
        acc[i] += __shfl_xor_sync(0xffffffffu, acc[i], 16);

    const float inv = 1.0f / (float)cnt;
    if (half == 0) {
        uint64_t q[4];
        #pragma unroll
        for (int i = 0; i < 4; ++i) {
            const uint32_t lo = __float_as_uint(acc[2 * i + 0] * inv);
            const uint32_t hi = __float_as_uint(acc[2 * i + 1] * inv);
            q[i] = (uint64_t)lo | ((uint64_t)hi << 32);
        }
        stg256_evf(out + (size_t)warp * ROW_BYTES + sub * 32,
                   q[0], q[1], q[2], q[3]);
    }
}

extern "C" void kernel_launch(void* const* d_in, const int* in_sizes, int n_in,
                              void* d_out, int out_size) {
    const int*   word_idx     = (const int*)d_in[0];   // [B*S]
    const int*   ngram_ids    = (const int*)d_in[1];   // [V*24]
    const int*   ngram_counts = (const int*)d_in[2];   // [V]
    const char*  emb_table    = (const char*)d_in[3];  // [NG*128] f32
    char*        outp         = (char*)d_out;

    const int n_words = in_sizes[0];                   // 32768
    const int threads = 256;                           // 8 warps / block
    const int warps_per_block = threads / 32;
    const int blocks = (n_words + warps_per_block - 1) / warps_per_block;

    ngram_emb_kernel<<<blocks, threads>>>(word_idx, ngram_ids, ngram_counts,
                                          emb_table, outp, n_words);
}